// round 2
// baseline (speedup 1.0000x reference)
#include <cuda_runtime.h>
#include <cuda_bf16.h>

// ---------------- problem constants ----------------
#define T_LEN   (1 << 21)              // 2,097,152 timesteps
#define L_STEPS 256                    // steps per chain
#define B_CHAINS (T_LEN / L_STEPS)     // 8192 chains
#define GPT 2                          // chains per thread (ILP)
#define SCAN_THREADS (B_CHAINS / GPT)  // 4096
#define SCAN_BLOCK 128
#define SCAN_GRID (SCAN_THREADS / SCAN_BLOCK)  // 32 blocks

#define RED_BLOCKS 1024
#define RED_THREADS 256

// ---------------- device scratch (no allocation allowed) ----------------
__device__ float2 g_tpte[T_LEN];          // warp-transposed (tanh(p_n/x1), tanh(e_n/x1))
__device__ float  g_send[2][B_CHAINS];    // ping-pong block end states
__device__ float  g_part[RED_BLOCKS * 8]; // reduction partials
__device__ float  g_stats[8];             // mu[4], inv_sigma[4]

// transposed index: chains grouped 32 per warp, step-major inside group
__device__ __forceinline__ int tr_idx(int c, int i) {
    return ((c >> 5) << 13) | (i << 5) | (c & 31);   // 32*L_STEPS = 8192 = 1<<13
}

// ---------------- one GR4J production-store step ----------------
__device__ __forceinline__ void gr_step(float& s, float tp, float tn,
                                        float& p_s_out, float& perc_out) {
    const float inv_x1 = 1.0f / 350.0f;
    float r   = s * inv_x1;
    // p_s = x1*(1-r^2)*tp / (1 + r*tp)
    float ps  = __fdividef(350.0f * (1.0f - r * r) * tp, fmaf(r, tp, 1.0f));
    // e_s = s*(2-r)*tn / (1 + (1-r)*tn)
    float es  = __fdividef(s * (2.0f - r) * tn, fmaf(1.0f - r, tn, 1.0f));
    float s1  = s + ps - es;
    // perc = s1*(1 - (1+u)^{-1/4}),  u = (4/9 * s1/x1)^4
    // cancellation-free: 1-w = u / (b*(1+w)*(1+w^2)),  w = b^{-1/4}, b = 1+u
    float y   = s1 * (4.0f / (9.0f * 350.0f));
    float y2  = y * y;
    float u   = y2 * y2;
    float b   = 1.0f + u;
    float q   = rsqrtf(b);          // b^{-1/2}
    float w   = q * rsqrtf(q);      // sqrt(q) = b^{-1/4}
    float den = b * (1.0f + w) * fmaf(w, w, 1.0f);
    float pc  = __fdividef(s1 * u, den);
    p_s_out  = ps;
    perc_out = pc;
    s = s1 - pc;
}

// ---------------- pass 0: elementwise prologue ----------------
__global__ void k_precompute(const float2* __restrict__ x, float* __restrict__ out) {
    int t = blockIdx.x * blockDim.x + threadIdx.x;
    float2 v = x[t];
    float pn = fmaxf(v.x - v.y, 0.0f);
    float en = fmaxf(v.y - v.x, 0.0f);
    reinterpret_cast<float2*>(out)[2 * t] = make_float2(pn, en);  // out cols 0,1 (raw)
    float tp = tanhf(pn * (1.0f / 350.0f));
    float te = tanhf(en * (1.0f / 350.0f));
    int c = t >> 8;          // t / L_STEPS
    int i = t & (L_STEPS - 1);
    g_tpte[tr_idx(c, i)] = make_float2(tp, te);
}

// ---------------- refinement pass: recompute block end states ----------------
__global__ void __launch_bounds__(SCAN_BLOCK) k_refine(int srcIdx, int dstIdx, int first) {
    int tid = blockIdx.x * blockDim.x + threadIdx.x;
    float s[GPT];
    int   base[GPT];
    int   c[GPT];
#pragma unroll
    for (int g = 0; g < GPT; g++) {
        c[g] = tid + g * SCAN_THREADS;
        base[g] = ((c[g] >> 5) << 13) | (c[g] & 31);
        s[g] = (first || c[g] == 0) ? 0.0f : g_send[srcIdx][c[g] - 1];
    }
#pragma unroll 4
    for (int i = 0; i < L_STEPS; i++) {
#pragma unroll
        for (int g = 0; g < GPT; g++) {
            float2 tt = g_tpte[base[g] + (i << 5)];
            float ps, pc;
            gr_step(s[g], tt.x, tt.y, ps, pc);
        }
    }
#pragma unroll
    for (int g = 0; g < GPT; g++) g_send[dstIdx][c[g]] = s[g];
}

// ---------------- final pass: replay scan, write outputs ----------------
__global__ void __launch_bounds__(SCAN_BLOCK) k_final(int srcIdx,
                                                      float* __restrict__ out,
                                                      float* __restrict__ sstore) {
    int tid = blockIdx.x * blockDim.x + threadIdx.x;
    float s[GPT];
    int   base[GPT];
    int   c[GPT];
#pragma unroll
    for (int g = 0; g < GPT; g++) {
        c[g] = tid + g * SCAN_THREADS;
        base[g] = ((c[g] >> 5) << 13) | (c[g] & 31);
        s[g] = (c[g] == 0) ? 0.0f : g_send[srcIdx][c[g] - 1];
    }
#pragma unroll 2
    for (int i = 0; i < L_STEPS; i++) {
#pragma unroll
        for (int g = 0; g < GPT; g++) {
            float2 tt = g_tpte[base[g] + (i << 5)];
            float ps, pc;
            gr_step(s[g], tt.x, tt.y, ps, pc);
            int t = c[g] * L_STEPS + i;
            reinterpret_cast<float2*>(out)[2 * t + 1] = make_float2(ps, pc); // cols 2,3
            sstore[t] = s[g];
        }
    }
}

// ---------------- deterministic column sums (stage 1) ----------------
__global__ void __launch_bounds__(RED_THREADS) k_reduce(const float4* __restrict__ out4) {
    float acc[8];
#pragma unroll
    for (int k = 0; k < 8; k++) acc[k] = 0.0f;
    for (int t = blockIdx.x * blockDim.x + threadIdx.x; t < T_LEN;
         t += gridDim.x * blockDim.x) {
        float4 v = out4[t];
        acc[0] += v.x; acc[1] += v.x * v.x;
        acc[2] += v.y; acc[3] += v.y * v.y;
        acc[4] += v.z; acc[5] += v.z * v.z;
        acc[6] += v.w; acc[7] += v.w * v.w;
    }
    __shared__ float sd[8][RED_THREADS];
    int tx = threadIdx.x;
#pragma unroll
    for (int k = 0; k < 8; k++) sd[k][tx] = acc[k];
    __syncthreads();
    for (int off = RED_THREADS / 2; off > 0; off >>= 1) {
        if (tx < off) {
#pragma unroll
            for (int k = 0; k < 8; k++) sd[k][tx] += sd[k][tx + off];
        }
        __syncthreads();
    }
    if (tx == 0) {
#pragma unroll
        for (int k = 0; k < 8; k++) g_part[blockIdx.x * 8 + k] = sd[k][0];
    }
}

// ---------------- stage 2: mu / inv_sigma ----------------
__global__ void __launch_bounds__(RED_THREADS) k_stats() {
    float acc[8];
#pragma unroll
    for (int k = 0; k < 8; k++) acc[k] = 0.0f;
    int tx = threadIdx.x;
    for (int b = tx; b < RED_BLOCKS; b += RED_THREADS) {
#pragma unroll
        for (int k = 0; k < 8; k++) acc[k] += g_part[b * 8 + k];
    }
    __shared__ float sd[8][RED_THREADS];
#pragma unroll
    for (int k = 0; k < 8; k++) sd[k][tx] = acc[k];
    __syncthreads();
    for (int off = RED_THREADS / 2; off > 0; off >>= 1) {
        if (tx < off) {
#pragma unroll
            for (int k = 0; k < 8; k++) sd[k][tx] += sd[k][tx + off];
        }
        __syncthreads();
    }
    if (tx == 0) {
        const float invT = 1.0f / (float)T_LEN;
#pragma unroll
        for (int k = 0; k < 4; k++) {
            float mu  = sd[2 * k][0] * invT;
            float var = sd[2 * k + 1][0] * invT - mu * mu;
            var = fmaxf(var, 0.0f);
            g_stats[k]     = mu;
            g_stats[4 + k] = 1.0f / sqrtf(var);
        }
    }
}

// ---------------- normalize out columns in place ----------------
__global__ void k_normalize(float4* __restrict__ out4) {
    __shared__ float st[8];
    if (threadIdx.x < 8) st[threadIdx.x] = g_stats[threadIdx.x];
    __syncthreads();
    int t = blockIdx.x * blockDim.x + threadIdx.x;
    float4 v = out4[t];
    v.x = (v.x - st[0]) * st[4];
    v.y = (v.y - st[1]) * st[5];
    v.z = (v.z - st[2]) * st[6];
    v.w = (v.w - st[3]) * st[7];
    out4[t] = v;
}

// ---------------- launch ----------------
extern "C" void kernel_launch(void* const* d_in, const int* in_sizes, int n_in,
                              void* d_out, int out_size) {
    (void)in_sizes; (void)n_in; (void)out_size;
    const float2* x = (const float2*)d_in[0];
    float* out    = (float*)d_out;                 // (T,4) row-major
    float* sstore = out + 4 * (size_t)T_LEN;       // (T,1) appended

    k_precompute<<<T_LEN / 256, 256>>>(x, out);

    // 4 relaxation sweeps over block end states (contraction >= e^-2.6 per sweep)
    k_refine<<<SCAN_GRID, SCAN_BLOCK>>>(0, 0, 1);
    k_refine<<<SCAN_GRID, SCAN_BLOCK>>>(0, 1, 0);
    k_refine<<<SCAN_GRID, SCAN_BLOCK>>>(1, 0, 0);
    k_refine<<<SCAN_GRID, SCAN_BLOCK>>>(0, 1, 0);

    k_final<<<SCAN_GRID, SCAN_BLOCK>>>(1, out, sstore);

    k_reduce<<<RED_BLOCKS, RED_THREADS>>>((const float4*)out);
    k_stats<<<1, RED_THREADS>>>();
    k_normalize<<<T_LEN / 256, 256>>>((float4*)out);
}

// round 3
// speedup vs baseline: 2.9690x; 2.9690x over previous
#include <cuda_runtime.h>
#include <cuda_bf16.h>

// ---------------- constants ----------------
#define T_LEN (1 << 21)          // 2,097,152
#define B_CH  8192               // chains (256 steps each)
#define NPRE  2048               // k_pre blocks
#define NREF  64                 // refine blocks (8192 chains / 128 thr)

// ---------------- device scratch ----------------
__device__ float4 g_all[T_LEN + 512];   // transposed (pn, en, tp, tn); padded for prefetch overrun
__device__ float  g_send[2][B_CH];      // ping-pong block end states
__device__ float  g_prepart[NPRE * 4];  // Σpn, Σpn², Σen, Σen² per block
__device__ float  g_spart[NREF * 4];    // Σps, Σps², Σpc, Σpc² per block
__device__ float  g_stats[8];           // mu[4], inv_sigma[4]

// transposed index: idx(C,i) = ((C>>5)<<13) | (i<<5) | (C&31)

// ---------------- MUFU-free GR4J production-store step ----------------
// Valid since tp,tn <= tanh(10/350)=0.02857 and 0 <= r < 1 (invariant).
__device__ __forceinline__ void gr_step(float& s, float tp, float tn,
                                        float& ps_o, float& pc_o) {
    const float INV = 1.0f / 350.0f;
    const float C49 = 4.0f / (9.0f * 350.0f);
    float r    = s * INV;
    // 1/(1+a) = (1-a)(1+a^2) + O(a^4),  a = r*tp <= 0.029
    float a    = r * tp;
    float oma  = 1.0f - a;
    float aa   = a * a;
    float hp   = fmaf(aa, oma, oma);
    float omr2 = fmaf(-r, r, 1.0f);
    float ps   = (omr2 * (350.0f * tp)) * hp;
    // 1/(1+be) = (1-be)(1+be^2),  be = (1-r)*tn <= 0.029
    float be   = fmaf(-r, tn, tn);
    float omb  = 1.0f - be;
    float bb   = be * be;
    float he   = fmaf(bb, omb, omb);
    float es   = (((2.0f - r)) * (s * tn)) * he;
    float s1   = (s + ps) - es;
    // 1-(1+u)^{-1/4} = u/4 - 5u^2/32 + 15u^3/128 - 195u^4/2048 + O(u^5), u <= 0.041
    float y    = s1 * C49;
    float y2   = y * y;
    float u    = y2 * y2;
    float t1   = fmaf(u, -0.15625f, 0.25f);
    float t2   = fmaf(u, -0.09521484375f, 0.1171875f);
    float u2   = u * u;
    float P    = fmaf(u2, t2, t1);
    float pc   = (s1 * u) * P;
    ps_o = ps; pc_o = pc;
    s = s1 - pc;
}

// ---------------- prologue: relu + tanh series + transpose + pn/en stats ----------------
__global__ void __launch_bounds__(256) k_pre(const float2* __restrict__ x) {
    __shared__ float4 tile[32][33];
    __shared__ float  red[4][256];
    int bid = blockIdx.x;
    int c0  = (bid >> 3) << 5;       // chain-group base (32 chains)
    int i0  = (bid & 7) << 5;        // step-tile base (32 steps)
    int tid = threadIdx.x;
    float a0 = 0.f, a1 = 0.f, a2 = 0.f, a3 = 0.f;
#pragma unroll
    for (int k = 0; k < 4; k++) {
        int e  = tid + (k << 8);
        int cc = e >> 5, ii = e & 31;
        float2 v = x[(c0 + cc) * 256 + i0 + ii];          // coalesced
        float pn = fmaxf(v.x - v.y, 0.0f);
        float en = fmaxf(v.y - v.x, 0.0f);
        // tanh(z) = z(1 - z^2/3 + 2z^4/15), z <= 0.0286 -> rel err ~3e-11
        float zp = pn * (1.0f / 350.0f), zp2 = zp * zp;
        float tp = zp * fmaf(zp2, fmaf(zp2, 0.13333333f, -0.33333333f), 1.0f);
        float ze = en * (1.0f / 350.0f), ze2 = ze * ze;
        float tn = ze * fmaf(ze2, fmaf(ze2, 0.13333333f, -0.33333333f), 1.0f);
        tile[cc][ii] = make_float4(pn, en, tp, tn);
        a0 += pn; a1 = fmaf(pn, pn, a1);
        a2 += en; a3 = fmaf(en, en, a3);
    }
    __syncthreads();
#pragma unroll
    for (int k = 0; k < 4; k++) {
        int e  = tid + (k << 8);
        int ii = e >> 5, cc = e & 31;
        g_all[((c0 >> 5) << 13) + ((i0 + ii) << 5) + cc] = tile[cc][ii];  // coalesced
    }
    red[0][tid] = a0; red[1][tid] = a1; red[2][tid] = a2; red[3][tid] = a3;
    __syncthreads();
    for (int o = 128; o > 0; o >>= 1) {
        if (tid < o) {
            red[0][tid] += red[0][tid + o]; red[1][tid] += red[1][tid + o];
            red[2][tid] += red[2][tid + o]; red[3][tid] += red[3][tid + o];
        }
        __syncthreads();
    }
    if (tid < 4) g_prepart[bid * 4 + tid] = red[tid][0];
}

// ---------------- refine pass (optionally accumulating ps/perc stats) ----------------
template <int FIRST, int STATS>
__global__ void __launch_bounds__(128) k_refine(int srcIdx, int dstIdx) {
    int C = blockIdx.x * 128 + threadIdx.x;
    const float4* p = g_all + (((C >> 5) << 13) | (C & 31));
    float s = (FIRST || C == 0) ? 0.0f : g_send[srcIdx][C - 1];
    float q0 = 0.f, q1 = 0.f, q2 = 0.f, q3 = 0.f;
    float4 A[8], B[8];
#pragma unroll
    for (int k = 0; k < 8; k++) A[k] = p[k << 5];
#pragma unroll
    for (int k = 0; k < 8; k++) B[k] = p[(8 + k) << 5];
#pragma unroll 1
    for (int i0 = 0; i0 < 256; i0 += 16) {
#pragma unroll
        for (int k = 0; k < 8; k++) {
            float ps, pc; gr_step(s, A[k].z, A[k].w, ps, pc);
            if (STATS) { q0 += ps; q1 = fmaf(ps, ps, q1); q2 += pc; q3 = fmaf(pc, pc, q3); }
        }
#pragma unroll
        for (int k = 0; k < 8; k++) A[k] = p[(i0 + 16 + k) << 5];   // pad absorbs tail overrun
#pragma unroll
        for (int k = 0; k < 8; k++) {
            float ps, pc; gr_step(s, B[k].z, B[k].w, ps, pc);
            if (STATS) { q0 += ps; q1 = fmaf(ps, ps, q1); q2 += pc; q3 = fmaf(pc, pc, q3); }
        }
#pragma unroll
        for (int k = 0; k < 8; k++) B[k] = p[(i0 + 24 + k) << 5];
    }
    g_send[dstIdx][C] = s;
    if (STATS) {
        __shared__ float rd[4][128];
        int tx = threadIdx.x;
        rd[0][tx] = q0; rd[1][tx] = q1; rd[2][tx] = q2; rd[3][tx] = q3;
        __syncthreads();
        for (int o = 64; o > 0; o >>= 1) {
            if (tx < o) {
                rd[0][tx] += rd[0][tx + o]; rd[1][tx] += rd[1][tx + o];
                rd[2][tx] += rd[2][tx + o]; rd[3][tx] += rd[3][tx + o];
            }
            __syncthreads();
        }
        if (tx < 4) g_spart[blockIdx.x * 4 + tx] = rd[tx][0];
    }
}

// ---------------- combine partials -> mu / inv_sigma ----------------
__global__ void __launch_bounds__(256) k_statsk() {
    __shared__ float sd[8][256];
    int tx = threadIdx.x;
    float acc[8] = {0, 0, 0, 0, 0, 0, 0, 0};
    for (int b = tx; b < NPRE; b += 256) {
        acc[0] += g_prepart[b * 4 + 0]; acc[1] += g_prepart[b * 4 + 1];
        acc[2] += g_prepart[b * 4 + 2]; acc[3] += g_prepart[b * 4 + 3];
    }
    for (int b = tx; b < NREF; b += 256) {
        acc[4] += g_spart[b * 4 + 0]; acc[5] += g_spart[b * 4 + 1];
        acc[6] += g_spart[b * 4 + 2]; acc[7] += g_spart[b * 4 + 3];
    }
#pragma unroll
    for (int k = 0; k < 8; k++) sd[k][tx] = acc[k];
    __syncthreads();
    for (int o = 128; o > 0; o >>= 1) {
        if (tx < o) {
#pragma unroll
            for (int k = 0; k < 8; k++) sd[k][tx] += sd[k][tx + o];
        }
        __syncthreads();
    }
    if (tx == 0) {
        const float invT = 1.0f / (float)T_LEN;
        float S[4]  = {sd[0][0], sd[2][0], sd[4][0], sd[6][0]};
        float S2[4] = {sd[1][0], sd[3][0], sd[5][0], sd[7][0]};
#pragma unroll
        for (int k = 0; k < 4; k++) {
            float mu  = S[k] * invT;
            float var = fmaxf(S2[k] * invT - mu * mu, 0.0f);
            g_stats[k]     = mu;
            g_stats[4 + k] = 1.0f / sqrtf(var);
        }
    }
}

// ---------------- final pass: compute 8 steps from BUF, stage, prefetch ----------------
__device__ __forceinline__ void f_phase(float& s, float4* BUF, const float4* p, int pre,
                                        float4 (*tout)[33], float (*tss)[33],
                                        int lane, int off, const float* st) {
#pragma unroll
    for (int k = 0; k < 8; k++) {
        float ps, pc; gr_step(s, BUF[k].z, BUF[k].w, ps, pc);
        tout[lane][off + k] = make_float4((BUF[k].x - st[0]) * st[4],
                                          (BUF[k].y - st[1]) * st[5],
                                          (ps - st[2]) * st[6],
                                          (pc - st[3]) * st[7]);
        tss[lane][off + k] = s;
    }
#pragma unroll
    for (int k = 0; k < 8; k++) BUF[k] = p[(pre + k) << 5];
}

__global__ void __launch_bounds__(32) k_final(float4* __restrict__ out, float* __restrict__ ss) {
    __shared__ float4 tout[32][33];
    __shared__ float  tss[32][33];
    int lane = threadIdx.x;
    int C = (blockIdx.x << 5) + lane;
    const float4* p = g_all + (blockIdx.x << 13) + lane;
    float s = (C == 0) ? 0.0f : g_send[1][C - 1];
    float st[8];
#pragma unroll
    for (int k = 0; k < 8; k++) st[k] = g_stats[k];
    float4 A[8], B[8];
#pragma unroll
    for (int k = 0; k < 8; k++) A[k] = p[k << 5];
#pragma unroll
    for (int k = 0; k < 8; k++) B[k] = p[(8 + k) << 5];
    int rowbase = blockIdx.x << 13;   // first row of this block's 32 chains
#pragma unroll 1
    for (int t0 = 0; t0 < 256; t0 += 32) {
        f_phase(s, A, p, t0 + 16, tout, tss, lane, 0,  st);
        f_phase(s, B, p, t0 + 24, tout, tss, lane, 8,  st);
        f_phase(s, A, p, t0 + 32, tout, tss, lane, 16, st);
        f_phase(s, B, p, t0 + 40, tout, tss, lane, 24, st);
        __syncwarp();
#pragma unroll 1
        for (int j = 0; j < 32; j++) {
            out[rowbase + j * 256 + t0 + lane] = tout[j][lane];   // 512B coalesced
            ss [rowbase + j * 256 + t0 + lane] = tss[j][lane];    // 128B coalesced
        }
        __syncwarp();
    }
}

// ---------------- launch ----------------
extern "C" void kernel_launch(void* const* d_in, const int* in_sizes, int n_in,
                              void* d_out, int out_size) {
    (void)in_sizes; (void)n_in; (void)out_size;
    const float2* x = (const float2*)d_in[0];
    float* out = (float*)d_out;                  // (T,4) row-major, normalized
    float* ssp = out + 4 * (size_t)T_LEN;        // (T,1) state trace

    k_pre<<<NPRE, 256>>>(x);
    k_refine<1, 0><<<NREF, 128>>>(0, 0);
    k_refine<0, 0><<<NREF, 128>>>(0, 1);
    k_refine<0, 0><<<NREF, 128>>>(1, 0);
    k_refine<0, 1><<<NREF, 128>>>(0, 1);   // stats pass (history 768 at entry)
    k_statsk<<<1, 256>>>();
    k_final<<<B_CH / 32, 32>>>((float4*)out, ssp);
}